// round 8
// baseline (speedup 1.0000x reference)
#include <cuda_runtime.h>
#include <math.h>
#include <stdint.h>
#include <mma.h>

using namespace nvcuda;

#define NQ      16384
#define CDIM    256
#define HEADS   8
#define HD      32
#define NPTS    4
#define NLAYERS 6
#define NCAM    6
#define HF      58
#define WF      100
#define NPIX    (HF*WF)
#define NFEAT   (NCAM*NPIX)
#define FFN     512

// ---------------- scratch ----------------------------------------------------
__device__ __align__(256) float g_q[NQ*CDIM];        // raw LN output (residual)
__device__ __align__(256) float g_q_rnd[NQ*CDIM];    // tf32-rounded (GEMM A)
__device__ __align__(256) float g_a[NQ*CDIM];        // rounded sampler output
__device__ __align__(256) float g_hid[NQ*FFN];       // rounded relu(ffn1)
__device__ __align__(256) float g_v[NQ*CDIM];
__device__ __align__(256) float g_vimg[NFEAT*CDIM];
__device__ __align__(256) float g_offattn[NQ*96];
__device__ __align__(256) float g_feats[NFEAT*CDIM]; // rounded
__device__ __align__(256) float g_refcam[NCAM*NQ*NPTS*2];
__device__ __align__(256) float g_valid[NCAM*NQ*NPTS];
__device__ __align__(256) float g_cnt[NQ];
__device__ __align__(256) float g_inv[NCAM*16];
// rounded weights (original (K,N) layout)
__device__ __align__(256) float g_tvw[NLAYERS*CDIM*CDIM];
__device__ __align__(256) float g_tpw[NLAYERS*CDIM*CDIM];
__device__ __align__(256) float g_svw[NLAYERS*CDIM*CDIM];
__device__ __align__(256) float g_spw[NLAYERS*CDIM*CDIM];
__device__ __align__(256) float g_f1w[NLAYERS*CDIM*FFN];
__device__ __align__(256) float g_f2w[NLAYERS*FFN*CDIM];
__device__ __align__(256) float g_oaw[2*NLAYERS*CDIM*128];
__device__ __align__(256) float g_oab[2*NLAYERS*128];

// ---------------- helpers ------------------------------------------------------
__device__ __forceinline__ float tf32r(float x) {
    float o;
    asm("cvt.rna.tf32.f32 %0, %1;" : "=f"(o) : "f"(x));
    return o;
}
__device__ __forceinline__ void cp_async16(void* sp, const void* gp) {
    uint32_t s = (uint32_t)__cvta_generic_to_shared(sp);
    asm volatile("cp.async.cg.shared.global [%0], [%1], 16;\n" :: "r"(s), "l"(gp));
}
__device__ __forceinline__ void cp_commit() { asm volatile("cp.async.commit_group;\n" ::: "memory"); }
template<int N> __device__ __forceinline__ void cp_wait() {
    asm volatile("cp.async.wait_group %0;\n" :: "n"(N) : "memory");
}

// ---------------- big tf32 GEMM: 128x128 tile, BK=32, double-buffered ----------
// EPI 0: +bias. EPI 1: +bias, relu, tf32-round.
// AVG: A-tile = tf32r(0.5*(A+A2)) loaded synchronously (B stays cp.async).
#define TBM 128
#define TBN 128
#define TBK 32
#define TLDA 40
#define TLDB 136
#define TA_ST (TBM*TLDA)   // 5120 floats
#define TB_ST (TBK*TLDB)   // 4352 floats
#define TLDC 132
#define T_SMEM ((2*(TA_ST+TB_ST))*4)   // 75776 B

template<int EPI, bool AVG>
__global__ __launch_bounds__(256) void k_gemm128(
    const float* __restrict__ A, const float* __restrict__ A2,
    const float* __restrict__ B,
    const float* __restrict__ bias, float* __restrict__ out,
    int M, int N, int K, int ldb)
{
    extern __shared__ float sm[];
    float* As = sm;
    float* Bs = sm + 2*TA_ST;
    float* Cs = sm;   // epilogue chunk reuse (64*132*4 = 33792 <= pipeline region)

    int tid = threadIdx.x;
    int wid = tid >> 5;
    int wr = wid & 1;    // 2 warp-rows (64 rows each)
    int wc = wid >> 1;   // 4 warp-cols (32 cols each)
    int m0 = blockIdx.x * TBM;
    int n0 = blockIdx.y * TBN;

    wmma::fragment<wmma::accumulator, 16, 16, 8, float> c[4][2];
    #pragma unroll
    for (int i = 0; i < 4; i++)
        #pragma unroll
        for (int j = 0; j < 2; j++)
            wmma::fill_fragment(c[i][j], 0.f);

    auto load_st = [&](int t, int b) {
        int k0 = t * TBK;
        float* as = As + b*TA_ST;
        float* bs = Bs + b*TB_ST;
        #pragma unroll
        for (int i = 0; i < 4; i++) {
            int cid = tid + i*256;
            int r = cid >> 3, c4 = cid & 7;
            int m = m0 + r; if (m >= M) m = M - 1;
            if (AVG) {
                float4 v1 = *(const float4*)&A[(size_t)m*K + k0 + c4*4];
                float4 v2 = *(const float4*)&A2[(size_t)m*K + k0 + c4*4];
                float4 v;
                v.x = tf32r(0.5f*(v1.x + v2.x));
                v.y = tf32r(0.5f*(v1.y + v2.y));
                v.z = tf32r(0.5f*(v1.z + v2.z));
                v.w = tf32r(0.5f*(v1.w + v2.w));
                *(float4*)&as[r*TLDA + c4*4] = v;
            } else {
                cp_async16(&as[r*TLDA + c4*4], &A[(size_t)m*K + k0 + c4*4]);
            }
        }
        #pragma unroll
        for (int i = 0; i < 4; i++) {
            int cid = tid + i*256;
            int r = cid >> 5, c4 = cid & 31;
            cp_async16(&bs[r*TLDB + c4*4], &B[(size_t)(k0 + r)*ldb + n0 + c4*4]);
        }
        cp_commit();
    };

    int T = K / TBK;
    load_st(0, 0);
    for (int t = 0; t < T; t++) {
        int b = t & 1;
        if (t + 1 < T) {
            load_st(t + 1, b ^ 1);
            cp_wait<1>();
        } else {
            cp_wait<0>();
        }
        __syncthreads();
        const float* as = As + b*TA_ST;
        const float* bs = Bs + b*TB_ST;
        #pragma unroll
        for (int kk = 0; kk < TBK; kk += 8) {
            wmma::fragment<wmma::matrix_a, 16, 16, 8, wmma::precision::tf32, wmma::row_major> a[4];
            wmma::fragment<wmma::matrix_b, 16, 16, 8, wmma::precision::tf32, wmma::row_major> bfrag[2];
            #pragma unroll
            for (int i = 0; i < 4; i++)
                wmma::load_matrix_sync(a[i], &as[(wr*64 + i*16)*TLDA + kk], TLDA);
            #pragma unroll
            for (int j = 0; j < 2; j++)
                wmma::load_matrix_sync(bfrag[j], &bs[kk*TLDB + wc*32 + j*16], TLDB);
            #pragma unroll
            for (int i = 0; i < 4; i++)
                #pragma unroll
                for (int j = 0; j < 2; j++)
                    wmma::mma_sync(c[i][j], a[i], bfrag[j], c[i][j]);
        }
        __syncthreads();
    }

    // chunked epilogue (64 rows at a time, reusing pipeline smem)
    int e4 = tid & 31, er = tid >> 5;
    int nn = n0 + e4*4;
    float4 bv = make_float4(0.f, 0.f, 0.f, 0.f);
    if (nn < N) bv = *(const float4*)&bias[nn];
    #pragma unroll
    for (int chunk = 0; chunk < 2; chunk++) {
        if (wr == chunk) {
            #pragma unroll
            for (int i = 0; i < 4; i++)
                #pragma unroll
                for (int j = 0; j < 2; j++)
                    wmma::store_matrix_sync(&Cs[(i*16)*TLDC + wc*32 + j*16],
                                            c[i][j], TLDC, wmma::mem_row_major);
        }
        __syncthreads();
        if (nn < N) {
            #pragma unroll
            for (int i = 0; i < 8; i++) {
                int r = er + i*8;
                int m = m0 + chunk*64 + r;
                if (m < M) {
                    float4 v = *(float4*)&Cs[r*TLDC + e4*4];
                    v.x += bv.x; v.y += bv.y; v.z += bv.z; v.w += bv.w;
                    if (EPI == 1) {
                        v.x = tf32r(fmaxf(v.x, 0.f)); v.y = tf32r(fmaxf(v.y, 0.f));
                        v.z = tf32r(fmaxf(v.z, 0.f)); v.w = tf32r(fmaxf(v.w, 0.f));
                    }
                    *(float4*)&out[(size_t)m*N + nn] = v;
                }
            }
        }
        __syncthreads();
    }
}

// ---------------- fused GEMM + residual + LN (N=256), BK=32 pipelined ----------
#define LM 64
#define LBK 32
#define LLDA 40
#define LLDB 264
#define LA_ST (LM*LLDA)    // 2560
#define LB_ST (LBK*LLDB)   // 8448
#define LLDC 260
#define L_SMEM ((2*(LA_ST+LB_ST))*4)   // 88064 B  (Cs 64*260*4=66560 fits)

__global__ __launch_bounds__(256) void k_gemm_ln(
    const float* __restrict__ A, const float* __restrict__ W,
    const float* __restrict__ bias, const float* __restrict__ resid,
    const float* __restrict__ gam, const float* __restrict__ bet,
    float* __restrict__ outp, float* __restrict__ ornd, int M, int K)
{
    extern __shared__ float sm[];
    float* As = sm;
    float* Bs = sm + 2*LA_ST;
    float* Cs = sm;

    int tid = threadIdx.x;
    int wid = tid >> 5;
    int lane = tid & 31;
    int wr = wid & 1;    // 2 warp-rows (32 rows)
    int wc = wid >> 1;   // 4 warp-cols (64 cols)
    int m0 = blockIdx.x * LM;

    wmma::fragment<wmma::accumulator, 16, 16, 8, float> c[2][4];
    #pragma unroll
    for (int i = 0; i < 2; i++)
        #pragma unroll
        for (int j = 0; j < 4; j++)
            wmma::fill_fragment(c[i][j], 0.f);

    auto load_st = [&](int t, int b) {
        int k0 = t * LBK;
        float* as = As + b*LA_ST;
        float* bs = Bs + b*LB_ST;
        #pragma unroll
        for (int i = 0; i < 2; i++) {
            int cid = tid + i*256;
            int r = cid >> 3, c4 = cid & 7;
            cp_async16(&as[r*LLDA + c4*4], &A[(size_t)(m0 + r)*K + k0 + c4*4]);
        }
        #pragma unroll
        for (int i = 0; i < 8; i++) {
            int cid = tid + i*256;
            int r = cid >> 6, c4 = cid & 63;
            cp_async16(&bs[r*LLDB + c4*4], &W[(size_t)(k0 + r)*CDIM + c4*4]);
        }
        cp_commit();
    };

    int T = K / LBK;
    load_st(0, 0);
    for (int t = 0; t < T; t++) {
        int b = t & 1;
        if (t + 1 < T) {
            load_st(t + 1, b ^ 1);
            cp_wait<1>();
        } else {
            cp_wait<0>();
        }
        __syncthreads();
        const float* as = As + b*LA_ST;
        const float* bs = Bs + b*LB_ST;
        #pragma unroll
        for (int kk = 0; kk < LBK; kk += 8) {
            wmma::fragment<wmma::matrix_a, 16, 16, 8, wmma::precision::tf32, wmma::row_major> a[2];
            wmma::fragment<wmma::matrix_b, 16, 16, 8, wmma::precision::tf32, wmma::row_major> bfrag[4];
            #pragma unroll
            for (int i = 0; i < 2; i++)
                wmma::load_matrix_sync(a[i], &as[(wr*32 + i*16)*LLDA + kk], LLDA);
            #pragma unroll
            for (int j = 0; j < 4; j++)
                wmma::load_matrix_sync(bfrag[j], &bs[kk*LLDB + wc*64 + j*16], LLDB);
            #pragma unroll
            for (int i = 0; i < 2; i++)
                #pragma unroll
                for (int j = 0; j < 4; j++)
                    wmma::mma_sync(c[i][j], a[i], bfrag[j], c[i][j]);
        }
        __syncthreads();
    }

    #pragma unroll
    for (int i = 0; i < 2; i++)
        #pragma unroll
        for (int j = 0; j < 4; j++)
            wmma::store_matrix_sync(&Cs[(wr*32 + i*16)*LLDC + wc*64 + j*16],
                                    c[i][j], LLDC, wmma::mem_row_major);
    __syncthreads();

    float4 bv0 = *(const float4*)&bias[lane*8];
    float4 bv1 = *(const float4*)&bias[lane*8 + 4];
    float4 gv0 = *(const float4*)&gam[lane*8];
    float4 gv1 = *(const float4*)&gam[lane*8 + 4];
    float4 tv0 = *(const float4*)&bet[lane*8];
    float4 tv1 = *(const float4*)&bet[lane*8 + 4];

    #pragma unroll
    for (int i = 0; i < 8; i++) {
        int r = wid*8 + i;
        int m = m0 + r;
        float4 c0 = *(float4*)&Cs[r*LLDC + lane*8];
        float4 c1 = *(float4*)&Cs[r*LLDC + lane*8 + 4];
        float4 q0 = *(const float4*)&resid[(size_t)m*CDIM + lane*8];
        float4 q1 = *(const float4*)&resid[(size_t)m*CDIM + lane*8 + 4];
        float x0 = q0.x + c0.x + bv0.x, x1 = q0.y + c0.y + bv0.y;
        float x2 = q0.z + c0.z + bv0.z, x3 = q0.w + c0.w + bv0.w;
        float x4 = q1.x + c1.x + bv1.x, x5 = q1.y + c1.y + bv1.y;
        float x6 = q1.z + c1.z + bv1.z, x7 = q1.w + c1.w + bv1.w;
        float s = x0+x1+x2+x3+x4+x5+x6+x7;
        #pragma unroll
        for (int o = 16; o > 0; o >>= 1) s += __shfl_xor_sync(0xffffffffu, s, o);
        float mean = s * (1.f/CDIM);
        float d0 = x0-mean, d1 = x1-mean, d2 = x2-mean, d3 = x3-mean;
        float d4 = x4-mean, d5 = x5-mean, d6 = x6-mean, d7 = x7-mean;
        float sq = d0*d0+d1*d1+d2*d2+d3*d3+d4*d4+d5*d5+d6*d6+d7*d7;
        #pragma unroll
        for (int o = 16; o > 0; o >>= 1) sq += __shfl_xor_sync(0xffffffffu, sq, o);
        float rstd = rsqrtf(sq * (1.f/CDIM) + 1e-5f);
        float o0 = d0*rstd*gv0.x + tv0.x, o1 = d1*rstd*gv0.y + tv0.y;
        float o2 = d2*rstd*gv0.z + tv0.z, o3 = d3*rstd*gv0.w + tv0.w;
        float o4 = d4*rstd*gv1.x + tv1.x, o5 = d5*rstd*gv1.y + tv1.y;
        float o6 = d6*rstd*gv1.z + tv1.z, o7 = d7*rstd*gv1.w + tv1.w;
        *(float4*)&outp[(size_t)m*CDIM + lane*8]     = make_float4(o0, o1, o2, o3);
        *(float4*)&outp[(size_t)m*CDIM + lane*8 + 4] = make_float4(o4, o5, o6, o7);
        *(float4*)&ornd[(size_t)m*CDIM + lane*8]     = make_float4(tf32r(o0), tf32r(o1), tf32r(o2), tf32r(o3));
        *(float4*)&ornd[(size_t)m*CDIM + lane*8 + 4] = make_float4(tf32r(o4), tf32r(o5), tf32r(o6), tf32r(o7));
    }
}

// ---------------- geometry / prep ------------------------------------------------
__global__ void k_invert(const float* __restrict__ extr) {
    int c = threadIdx.x;
    if (c >= NCAM) return;
    float a[4][8];
    for (int i = 0; i < 4; i++)
        for (int j = 0; j < 4; j++) {
            a[i][j] = extr[c*16 + i*4 + j];
            a[i][j+4] = (i == j) ? 1.f : 0.f;
        }
    for (int col = 0; col < 4; col++) {
        int piv = col;
        for (int r = col+1; r < 4; r++)
            if (fabsf(a[r][col]) > fabsf(a[piv][col])) piv = r;
        if (piv != col)
            for (int j = 0; j < 8; j++) { float t = a[col][j]; a[col][j] = a[piv][j]; a[piv][j] = t; }
        float d = 1.f / a[col][col];
        for (int j = 0; j < 8; j++) a[col][j] *= d;
        for (int r = 0; r < 4; r++) {
            if (r == col) continue;
            float f = a[r][col];
            for (int j = 0; j < 8; j++) a[r][j] -= f * a[col][j];
        }
    }
    for (int i = 0; i < 4; i++)
        for (int j = 0; j < 4; j++)
            g_inv[c*16 + i*4 + j] = a[i][j+4];
}

__global__ void k_geom(const float* __restrict__ intr) {
    int idx = blockIdx.x * blockDim.x + threadIdx.x;
    if (idx >= NCAM*NQ*NPTS) return;
    int p = idx % NPTS;
    int n = (idx / NPTS) % NQ;
    int c = idx / (NPTS * NQ);
    float gx = ((n & 127) + 0.5f) / 128.f;
    float gy = ((n >> 7)  + 0.5f) / 128.f;
    float xm = -51.2f + gx * 102.4f;
    float ym = -51.2f + gy * 102.4f;
    float zm = -5.0f + (p + 0.5f) * 2.0f;
    const float* Mi = &g_inv[c*16];
    float px = Mi[0]*xm + Mi[1]*ym + Mi[2]*zm  + Mi[3];
    float py = Mi[4]*xm + Mi[5]*ym + Mi[6]*zm  + Mi[7];
    float pz = Mi[8]*xm + Mi[9]*ym + Mi[10]*zm + Mi[11];
    const float* I = &intr[c*9];
    float ix = I[0]*px + I[1]*py + I[2]*pz;
    float iy = I[3]*px + I[4]*py + I[5]*pz;
    float iz = I[6]*px + I[7]*py + I[8]*pz;
    float zc = fmaxf(iz, 1e-5f);
    float un = ix / (zc * WF);
    float vn = iy / (zc * HF);
    float val = (iz > 1e-5f && un >= 0.f && un <= 1.f && vn >= 0.f && vn <= 1.f) ? 1.f : 0.f;
    g_refcam[idx*2+0] = un;
    g_refcam[idx*2+1] = vn;
    g_valid[idx] = val;
}

__global__ void k_cnt() {
    int n = blockIdx.x * blockDim.x + threadIdx.x;
    if (n >= NQ) return;
    float s = 0.f;
    for (int c = 0; c < NCAM; c++)
        for (int p = 0; p < NPTS; p++)
            s += g_valid[(c*NQ + n)*NPTS + p];
    g_cnt[n] = fmaxf(s, 1.f);
}

__global__ void k_feats_t(const float* __restrict__ in) {
    __shared__ float tile[32][33];
    int pix0 = blockIdx.x * 32, ch0 = blockIdx.y * 32, c = blockIdx.z;
    int tx = threadIdx.x, ty = threadIdx.y;
    for (int i = ty; i < 32; i += 8) {
        int pix = pix0 + tx;
        tile[i][tx] = (pix < NPIX) ? in[((size_t)c*CDIM + ch0 + i)*NPIX + pix] : 0.f;
    }
    __syncthreads();
    for (int i = ty; i < 32; i += 8) {
        int pix = pix0 + i;
        if (pix < NPIX)
            g_feats[((size_t)c*NPIX + pix)*CDIM + ch0 + tx] = tf32r(tile[tx][i]);
    }
}

__global__ void k_round(const float* __restrict__ W, float* __restrict__ out, int n) {
    int i = blockIdx.x * blockDim.x + threadIdx.x;
    if (i < n) out[i] = tf32r(W[i]);
}

__global__ void k_prep_oa(const float* __restrict__ tow, const float* __restrict__ taw,
                          const float* __restrict__ sow, const float* __restrict__ saw,
                          const float* __restrict__ tob, const float* __restrict__ tab,
                          const float* __restrict__ sob, const float* __restrict__ sab) {
    int idx = blockIdx.x * blockDim.x + threadIdx.x;
    int total = 2*NLAYERS*CDIM*128;
    if (idx < total) {
        int n = idx % 128;
        int k = (idx / 128) % CDIM;
        int l = (idx / (128*CDIM)) % NLAYERS;
        int s = idx / (128*CDIM*NLAYERS);
        const float* ow = s ? sow : tow;
        const float* aw = s ? saw : taw;
        float w = 0.f;
        if (n < 64)      w = ow[((size_t)l*CDIM + k)*64 + n];
        else if (n < 96) w = aw[((size_t)l*CDIM + k)*32 + (n - 64)];
        g_oaw[idx] = tf32r(w);
    }
    if (idx < 2*NLAYERS*128) {
        int j = idx % 128;
        int l = (idx / 128) % NLAYERS;
        int s = idx / (128*NLAYERS);
        const float* ob = s ? sob : tob;
        const float* ab = s ? sab : tab;
        float b = 0.f;
        if (j < 64)      b = ob[l*64 + j];
        else if (j < 96) b = ab[l*32 + (j - 64)];
        g_oab[idx] = b;
    }
}

__global__ void k_init_q(const float* __restrict__ src) {
    int i = blockIdx.x * blockDim.x + threadIdx.x;
    if (i >= NQ*CDIM) return;
    float v = src[i];
    g_q[i] = v;
    g_q_rnd[i] = tf32r(v);
}

// ---------------- samplers --------------------------------------------------------
__device__ __forceinline__ float bilin(const float* __restrict__ base, int H, int W,
                                       int stride, float ix, float iy) {
    float x0f = floorf(ix), y0f = floorf(iy);
    int x0 = (int)x0f, y0 = (int)y0f;
    float fx = ix - x0f, fy = iy - y0f;
    float out = 0.f;
    #pragma unroll
    for (int dy = 0; dy < 2; dy++) {
        int yi = y0 + dy;
        if (yi < 0 || yi >= H) continue;
        float wy = dy ? fy : 1.f - fy;
        #pragma unroll
        for (int dx = 0; dx < 2; dx++) {
            int xi = x0 + dx;
            if (xi < 0 || xi >= W) continue;
            float wx = dx ? fx : 1.f - fx;
            out += wy * wx * base[((size_t)yi*W + xi) * stride];
        }
    }
    return out;
}

__global__ void k_tsa_sample() {
    int n = blockIdx.x;
    int h = threadIdx.x >> 5;
    int lane = threadIdx.x & 31;
    const float* oa = &g_offattn[n*96];
    float lg0 = oa[64 + h*4 + 0], lg1 = oa[64 + h*4 + 1];
    float lg2 = oa[64 + h*4 + 2], lg3 = oa[64 + h*4 + 3];
    float mx = fmaxf(fmaxf(lg0, lg1), fmaxf(lg2, lg3));
    float e0 = expf(lg0-mx), e1 = expf(lg1-mx), e2 = expf(lg2-mx), e3 = expf(lg3-mx);
    float rse = 1.f / (e0+e1+e2+e3);
    float w[4] = {e0*rse, e1*rse, e2*rse, e3*rse};
    float refx = ((n & 127) + 0.5f);
    float refy = ((n >> 7)  + 0.5f);
    const float* base = g_v + h*HD + lane;
    float acc = 0.f;
    #pragma unroll
    for (int p = 0; p < 4; p++) {
        float ox = oa[(h*4 + p)*2 + 0];
        float oy = oa[(h*4 + p)*2 + 1];
        acc += w[p] * bilin(base, 128, 128, CDIM, refx + ox - 0.5f, refy + oy - 0.5f);
    }
    g_a[(size_t)n*CDIM + h*HD + lane] = tf32r(acc);
}

__global__ void k_sca_sample() {
    int n = blockIdx.x;
    int h = threadIdx.x >> 5;
    int lane = threadIdx.x & 31;
    const float* oa = &g_offattn[n*96];
    float lg0 = oa[64 + h*4 + 0], lg1 = oa[64 + h*4 + 1];
    float lg2 = oa[64 + h*4 + 2], lg3 = oa[64 + h*4 + 3];
    float mx = fmaxf(fmaxf(lg0, lg1), fmaxf(lg2, lg3));
    float e0 = expf(lg0-mx), e1 = expf(lg1-mx), e2 = expf(lg2-mx), e3 = expf(lg3-mx);
    float rse = 1.f / (e0+e1+e2+e3);
    float w[4], ox[4], oy[4];
    w[0] = e0*rse; w[1] = e1*rse; w[2] = e2*rse; w[3] = e3*rse;
    #pragma unroll
    for (int p = 0; p < 4; p++) {
        ox[p] = oa[(h*4 + p)*2 + 0];
        oy[p] = oa[(h*4 + p)*2 + 1];
    }
    float acc = 0.f;
    for (int c = 0; c < NCAM; c++) {
        const float* rc = &g_refcam[((size_t)(c*NQ + n))*NPTS*2];
        const float* vv = &g_valid[((size_t)(c*NQ + n))*NPTS];
        const float* base = g_vimg + (size_t)c*NPIX*CDIM + h*HD + lane;
        #pragma unroll
        for (int p = 0; p < 4; p++) {
            if (vv[p] == 0.f) continue;
            float ix = rc[p*2+0]*WF + ox[p] - 0.5f;
            float iy = rc[p*2+1]*HF + oy[p] - 0.5f;
            acc += w[p] * bilin(base, HF, WF, CDIM, ix, iy);
        }
    }
    g_a[(size_t)n*CDIM + h*HD + lane] = tf32r(acc / g_cnt[n]);
}

__global__ void k_out_t(float* __restrict__ out) {
    __shared__ float tile[32][33];
    int n0 = blockIdx.x * 32, c0 = blockIdx.y * 32;
    int tx = threadIdx.x, ty = threadIdx.y;
    for (int i = ty; i < 32; i += 8)
        tile[i][tx] = g_q[(size_t)(n0 + i)*CDIM + c0 + tx];
    __syncthreads();
    for (int i = ty; i < 32; i += 8)
        out[(size_t)(c0 + i)*NQ + n0 + tx] = tile[tx][i];
}

// ---------------- host --------------------------------------------------------
static void gemm128(const float* A, const float* B, const float* bias, float* out,
                    int M, int N, int K, int ldb, bool relu) {
    dim3 g((M + TBM - 1) / TBM, (ldb + TBN - 1) / TBN);
    if (relu) k_gemm128<1, false><<<g, 256, T_SMEM>>>(A, A, B, bias, out, M, N, K, ldb);
    else      k_gemm128<0, false><<<g, 256, T_SMEM>>>(A, A, B, bias, out, M, N, K, ldb);
}
static void gemm128_avg(const float* A, const float* A2, const float* B,
                        const float* bias, float* out, int M, int N, int K, int ldb) {
    dim3 g((M + TBM - 1) / TBM, (ldb + TBN - 1) / TBN);
    k_gemm128<0, true><<<g, 256, T_SMEM>>>(A, A2, B, bias, out, M, N, K, ldb);
}
static void gemm_ln(const float* A, const float* W, const float* bias,
                    const float* resid, const float* gam, const float* bet,
                    float* outp, float* ornd, int M, int K) {
    k_gemm_ln<<<M / LM, 256, L_SMEM>>>(A, W, bias, resid, gam, bet, outp, ornd, M, K);
}

extern "C" void kernel_launch(void* const* d_in, const int* in_sizes, int n_in,
                              void* d_out, int out_size) {
    static bool attr_set = false;
    if (!attr_set) {
        cudaFuncSetAttribute((const void*)k_gemm128<0, false>, cudaFuncAttributeMaxDynamicSharedMemorySize, T_SMEM);
        cudaFuncSetAttribute((const void*)k_gemm128<1, false>, cudaFuncAttributeMaxDynamicSharedMemorySize, T_SMEM);
        cudaFuncSetAttribute((const void*)k_gemm128<0, true>,  cudaFuncAttributeMaxDynamicSharedMemorySize, T_SMEM);
        cudaFuncSetAttribute((const void*)k_gemm_ln,           cudaFuncAttributeMaxDynamicSharedMemorySize, L_SMEM);
        attr_set = true;
    }

    const float* image_feats = (const float*)d_in[0];
    const float* intr        = (const float*)d_in[1];
    const float* extr        = (const float*)d_in[2];
    const float* prev        = (const float*)d_in[3];
    const float* bev         = (const float*)d_in[4];
    const float* tsa_vw = (const float*)d_in[5];
    const float* tsa_vb = (const float*)d_in[6];
    const float* tsa_pw = (const float*)d_in[11];
    const float* tsa_pb = (const float*)d_in[12];
    const float* sca_vw = (const float*)d_in[13];
    const float* sca_vb = (const float*)d_in[14];
    const float* sca_pw = (const float*)d_in[19];
    const float* sca_pb = (const float*)d_in[20];
    const float* ffn_w1 = (const float*)d_in[21];
    const float* ffn_b1 = (const float*)d_in[22];
    const float* ffn_w2 = (const float*)d_in[23];
    const float* ffn_b2 = (const float*)d_in[24];
    const float* ln1_g  = (const float*)d_in[25];
    const float* ln1_b  = (const float*)d_in[26];
    const float* ln2_g  = (const float*)d_in[27];
    const float* ln2_b  = (const float*)d_in[28];
    const float* ln3_g  = (const float*)d_in[29];
    const float* ln3_b  = (const float*)d_in[30];

    float *q_, *qr_, *a_, *hid_, *v_, *vimg_, *oa_, *feats_;
    float *tvw_, *tpw_, *svw_, *spw_, *f1w_, *f2w_, *oaw_, *oab_;
    cudaGetSymbolAddress((void**)&q_,    g_q);
    cudaGetSymbolAddress((void**)&qr_,   g_q_rnd);
    cudaGetSymbolAddress((void**)&a_,    g_a);
    cudaGetSymbolAddress((void**)&hid_,  g_hid);
    cudaGetSymbolAddress((void**)&v_,    g_v);
    cudaGetSymbolAddress((void**)&vimg_, g_vimg);
    cudaGetSymbolAddress((void**)&oa_,   g_offattn);
    cudaGetSymbolAddress((void**)&feats_, g_feats);
    cudaGetSymbolAddress((void**)&tvw_,  g_tvw);
    cudaGetSymbolAddress((void**)&tpw_,  g_tpw);
    cudaGetSymbolAddress((void**)&svw_,  g_svw);
    cudaGetSymbolAddress((void**)&spw_,  g_spw);
    cudaGetSymbolAddress((void**)&f1w_,  g_f1w);
    cudaGetSymbolAddress((void**)&f2w_,  g_f2w);
    cudaGetSymbolAddress((void**)&oaw_,  g_oaw);
    cudaGetSymbolAddress((void**)&oab_,  g_oab);

    const int WB = 256;
    {
        dim3 gt((NPIX + 31)/32, CDIM/32, NCAM);
        k_feats_t<<<gt, dim3(32, 8)>>>(image_feats);                      // 1
    }
    k_round<<<(NLAYERS*CDIM*CDIM + WB-1)/WB, WB>>>(sca_vw, svw_, NLAYERS*CDIM*CDIM);  // 2
    k_invert<<<1, NCAM>>>(extr);                                          // 3
    gemm128(feats_, svw_, sca_vb, vimg_, NFEAT, CDIM, CDIM, CDIM, false); // 4 (profile slot)
    k_geom<<<(NCAM*NQ*NPTS + 255)/256, 256>>>(intr);
    k_cnt<<<(NQ + 255)/256, 256>>>();
    k_round<<<(NLAYERS*CDIM*CDIM + WB-1)/WB, WB>>>(tsa_vw, tvw_, NLAYERS*CDIM*CDIM);
    k_round<<<(NLAYERS*CDIM*CDIM + WB-1)/WB, WB>>>(tsa_pw, tpw_, NLAYERS*CDIM*CDIM);
    k_round<<<(NLAYERS*CDIM*CDIM + WB-1)/WB, WB>>>(sca_pw, spw_, NLAYERS*CDIM*CDIM);
    k_round<<<(NLAYERS*CDIM*FFN + WB-1)/WB, WB>>>(ffn_w1, f1w_, NLAYERS*CDIM*FFN);
    k_round<<<(NLAYERS*FFN*CDIM + WB-1)/WB, WB>>>(ffn_w2, f2w_, NLAYERS*FFN*CDIM);
    k_prep_oa<<<(2*NLAYERS*CDIM*128 + WB-1)/WB, WB>>>(
        (const float*)d_in[7], (const float*)d_in[9],
        (const float*)d_in[15], (const float*)d_in[17],
        (const float*)d_in[8], (const float*)d_in[10],
        (const float*)d_in[16], (const float*)d_in[18]);
    k_init_q<<<(NQ*CDIM + 255)/256, 256>>>(bev);

    for (int l = 0; l < NLAYERS; l++) {
        size_t wo = (size_t)l*CDIM*CDIM;
        // ---- TSA ----
        gemm128_avg(q_, prev, tvw_ + wo, tsa_vb + l*CDIM, v_, NQ, CDIM, CDIM, CDIM);
        gemm128(qr_, oaw_ + (size_t)l*CDIM*128, oab_ + l*128, oa_, NQ, 96, CDIM, 128, false);
        k_tsa_sample<<<NQ, 256>>>();
        gemm_ln(a_, tpw_ + wo, tsa_pb + l*CDIM, q_, ln1_g + l*CDIM, ln1_b + l*CDIM,
                q_, qr_, NQ, CDIM);

        // ---- SCA ----
        if (l > 0)
            gemm128(feats_, svw_ + wo, sca_vb + l*CDIM, vimg_, NFEAT, CDIM, CDIM, CDIM, false);
        gemm128(qr_, oaw_ + (size_t)(NLAYERS + l)*CDIM*128, oab_ + (NLAYERS + l)*128,
                oa_, NQ, 96, CDIM, 128, false);
        k_sca_sample<<<NQ, 256>>>();
        gemm_ln(a_, spw_ + wo, sca_pb + l*CDIM, q_, ln2_g + l*CDIM, ln2_b + l*CDIM,
                q_, qr_, NQ, CDIM);

        // ---- FFN ----
        gemm128(qr_, f1w_ + (size_t)l*CDIM*FFN, ffn_b1 + l*FFN, hid_, NQ, FFN, CDIM, FFN, true);
        gemm_ln(hid_, f2w_ + (size_t)l*FFN*CDIM, ffn_b2 + l*CDIM, q_,
                ln3_g + l*CDIM, ln3_b + l*CDIM, q_, qr_, NQ, FFN);
    }

    k_out_t<<<dim3(NQ/32, CDIM/32), dim3(32, 8)>>>((float*)d_out);
}

// round 9
// speedup vs baseline: 1.0734x; 1.0734x over previous
#include <cuda_runtime.h>
#include <math.h>
#include <stdint.h>
#include <mma.h>

using namespace nvcuda;

#define NQ      16384
#define CDIM    256
#define HEADS   8
#define HD      32
#define NPTS    4
#define NLAYERS 6
#define NCAM    6
#define HF      58
#define WF      100
#define NPIX    (HF*WF)
#define NFEAT   (NCAM*NPIX)
#define FFN     512

// ---------------- scratch ----------------------------------------------------
__device__ __align__(256) float g_q[NQ*CDIM];
__device__ __align__(256) float g_q_rnd[NQ*CDIM];
__device__ __align__(256) float g_a[NQ*CDIM];
__device__ __align__(256) float g_hid[NQ*FFN];
__device__ __align__(256) float g_v[NQ*CDIM];
__device__ __align__(256) float g_vimg[NFEAT*CDIM];
__device__ __align__(256) float g_offattn[NQ*96];
__device__ __align__(256) float g_feats[NFEAT*CDIM];
__device__ __align__(256) float g_refcam[NCAM*NQ*NPTS*2];
__device__ __align__(256) float g_valid[NCAM*NQ*NPTS];
__device__ __align__(256) float g_cnt[NQ];
__device__ __align__(256) float g_inv[NCAM*16];
__device__ __align__(256) float g_tvw[NLAYERS*CDIM*CDIM];
__device__ __align__(256) float g_tpw[NLAYERS*CDIM*CDIM];
__device__ __align__(256) float g_svw[NLAYERS*CDIM*CDIM];
__device__ __align__(256) float g_spw[NLAYERS*CDIM*CDIM];
__device__ __align__(256) float g_f1w[NLAYERS*CDIM*FFN];
__device__ __align__(256) float g_f2w[NLAYERS*FFN*CDIM];
__device__ __align__(256) float g_oaw[2*NLAYERS*CDIM*128];
__device__ __align__(256) float g_oab[2*NLAYERS*128];

// ---------------- helpers ------------------------------------------------------
__device__ __forceinline__ float tf32r(float x) {
    float o;
    asm("cvt.rna.tf32.f32 %0, %1;" : "=f"(o) : "f"(x));
    return o;
}
__device__ __forceinline__ void cp_async16(void* sp, const void* gp) {
    uint32_t s = (uint32_t)__cvta_generic_to_shared(sp);
    asm volatile("cp.async.cg.shared.global [%0], [%1], 16;\n" :: "r"(s), "l"(gp));
}
__device__ __forceinline__ void cp_commit() { asm volatile("cp.async.commit_group;\n" ::: "memory"); }
template<int N> __device__ __forceinline__ void cp_wait() {
    asm volatile("cp.async.wait_group %0;\n" :: "n"(N) : "memory");
}

// ---------------- big tf32 GEMM: 128x128 tile, BK=32, double-buffered ----------
#define TBM 128
#define TBN 128
#define TBK 32
#define TLDA 40
#define TLDB 136
#define TA_ST (TBM*TLDA)
#define TB_ST (TBK*TLDB)
#define TLDC 132
#define T_SMEM ((2*(TA_ST+TB_ST))*4)   // 75776 B

template<int EPI, bool AVG>
__global__ __launch_bounds__(256, 2) void k_gemm128(
    const float* __restrict__ A, const float* __restrict__ A2,
    const float* __restrict__ B,
    const float* __restrict__ bias, float* __restrict__ out,
    int M, int N, int K, int ldb)
{
    extern __shared__ float sm[];
    float* As = sm;
    float* Bs = sm + 2*TA_ST;
    float* Cs = sm;

    int tid = threadIdx.x;
    int wid = tid >> 5;
    int wr = wid & 1;
    int wc = wid >> 1;
    int m0 = blockIdx.x * TBM;
    int n0 = blockIdx.y * TBN;

    wmma::fragment<wmma::accumulator, 16, 16, 8, float> c[4][2];
    #pragma unroll
    for (int i = 0; i < 4; i++)
        #pragma unroll
        for (int j = 0; j < 2; j++)
            wmma::fill_fragment(c[i][j], 0.f);

    auto load_st = [&](int t, int b) {
        int k0 = t * TBK;
        float* as = As + b*TA_ST;
        float* bs = Bs + b*TB_ST;
        #pragma unroll
        for (int i = 0; i < 4; i++) {
            int cid = tid + i*256;
            int r = cid >> 3, c4 = cid & 7;
            int m = m0 + r; if (m >= M) m = M - 1;
            if (AVG) {
                float4 v1 = *(const float4*)&A[(size_t)m*K + k0 + c4*4];
                float4 v2 = *(const float4*)&A2[(size_t)m*K + k0 + c4*4];
                float4 v;
                v.x = tf32r(0.5f*(v1.x + v2.x));
                v.y = tf32r(0.5f*(v1.y + v2.y));
                v.z = tf32r(0.5f*(v1.z + v2.z));
                v.w = tf32r(0.5f*(v1.w + v2.w));
                *(float4*)&as[r*TLDA + c4*4] = v;
            } else {
                cp_async16(&as[r*TLDA + c4*4], &A[(size_t)m*K + k0 + c4*4]);
            }
        }
        #pragma unroll
        for (int i = 0; i < 4; i++) {
            int cid = tid + i*256;
            int r = cid >> 5, c4 = cid & 31;
            cp_async16(&bs[r*TLDB + c4*4], &B[(size_t)(k0 + r)*ldb + n0 + c4*4]);
        }
        cp_commit();
    };

    int T = K / TBK;
    load_st(0, 0);
    for (int t = 0; t < T; t++) {
        int b = t & 1;
        if (t + 1 < T) {
            load_st(t + 1, b ^ 1);
            cp_wait<1>();
        } else {
            cp_wait<0>();
        }
        __syncthreads();
        const float* as = As + b*TA_ST;
        const float* bs = Bs + b*TB_ST;
        #pragma unroll
        for (int kk = 0; kk < TBK; kk += 8) {
            wmma::fragment<wmma::matrix_a, 16, 16, 8, wmma::precision::tf32, wmma::row_major> a[4];
            wmma::fragment<wmma::matrix_b, 16, 16, 8, wmma::precision::tf32, wmma::row_major> bfrag[2];
            #pragma unroll
            for (int i = 0; i < 4; i++)
                wmma::load_matrix_sync(a[i], &as[(wr*64 + i*16)*TLDA + kk], TLDA);
            #pragma unroll
            for (int j = 0; j < 2; j++)
                wmma::load_matrix_sync(bfrag[j], &bs[kk*TLDB + wc*32 + j*16], TLDB);
            #pragma unroll
            for (int i = 0; i < 4; i++)
                #pragma unroll
                for (int j = 0; j < 2; j++)
                    wmma::mma_sync(c[i][j], a[i], bfrag[j], c[i][j]);
        }
        __syncthreads();
    }

    // chunked epilogue (64 rows at a time)
    int e4 = tid & 31, er = tid >> 5;
    int nn = n0 + e4*4;
    float4 bv = make_float4(0.f, 0.f, 0.f, 0.f);
    if (nn < N) bv = *(const float4*)&bias[nn];
    #pragma unroll
    for (int chunk = 0; chunk < 2; chunk++) {
        if (wr == chunk) {
            #pragma unroll
            for (int i = 0; i < 4; i++)
                #pragma unroll
                for (int j = 0; j < 2; j++)
                    wmma::store_matrix_sync(&Cs[(i*16)*TLDC + wc*32 + j*16],
                                            c[i][j], TLDC, wmma::mem_row_major);
        }
        __syncthreads();
        if (nn < N) {
            #pragma unroll
            for (int i = 0; i < 8; i++) {
                int r = er + i*8;
                int m = m0 + chunk*64 + r;
                if (m < M) {
                    float4 v = *(float4*)&Cs[r*TLDC + e4*4];
                    v.x += bv.x; v.y += bv.y; v.z += bv.z; v.w += bv.w;
                    if (EPI == 1) {
                        v.x = tf32r(fmaxf(v.x, 0.f)); v.y = tf32r(fmaxf(v.y, 0.f));
                        v.z = tf32r(fmaxf(v.z, 0.f)); v.w = tf32r(fmaxf(v.w, 0.f));
                    }
                    *(float4*)&out[(size_t)m*N + nn] = v;
                }
            }
        }
        __syncthreads();
    }
}

// ---------------- fused GEMM + residual + LN (N=256), BK=32 pipelined ----------
#define LM 64
#define LBK 32
#define LLDA 40
#define LLDB 264
#define LA_ST (LM*LLDA)
#define LB_ST (LBK*LLDB)
#define LLDC 260
#define L_SMEM ((2*(LA_ST+LB_ST))*4)   // 88064 B

__global__ __launch_bounds__(256, 2) void k_gemm_ln(
    const float* __restrict__ A, const float* __restrict__ W,
    const float* __restrict__ bias, const float* __restrict__ resid,
    const float* __restrict__ gam, const float* __restrict__ bet,
    float* __restrict__ outp, float* __restrict__ ornd, int M, int K)
{
    extern __shared__ float sm[];
    float* As = sm;
    float* Bs = sm + 2*LA_ST;
    float* Cs = sm;

    int tid = threadIdx.x;
    int wid = tid >> 5;
    int lane = tid & 31;
    int wr = wid & 1;
    int wc = wid >> 1;
    int m0 = blockIdx.x * LM;

    wmma::fragment<wmma::accumulator, 16, 16, 8, float> c[2][4];
    #pragma unroll
    for (int i = 0; i < 2; i++)
        #pragma unroll
        for (int j = 0; j < 4; j++)
            wmma::fill_fragment(c[i][j], 0.f);

    auto load_st = [&](int t, int b) {
        int k0 = t * LBK;
        float* as = As + b*LA_ST;
        float* bs = Bs + b*LB_ST;
        #pragma unroll
        for (int i = 0; i < 2; i++) {
            int cid = tid + i*256;
            int r = cid >> 3, c4 = cid & 7;
            cp_async16(&as[r*LLDA + c4*4], &A[(size_t)(m0 + r)*K + k0 + c4*4]);
        }
        #pragma unroll
        for (int i = 0; i < 8; i++) {
            int cid = tid + i*256;
            int r = cid >> 6, c4 = cid & 63;
            cp_async16(&bs[r*LLDB + c4*4], &W[(size_t)(k0 + r)*CDIM + c4*4]);
        }
        cp_commit();
    };

    int T = K / LBK;
    load_st(0, 0);
    for (int t = 0; t < T; t++) {
        int b = t & 1;
        if (t + 1 < T) {
            load_st(t + 1, b ^ 1);
            cp_wait<1>();
        } else {
            cp_wait<0>();
        }
        __syncthreads();
        const float* as = As + b*LA_ST;
        const float* bs = Bs + b*LB_ST;
        #pragma unroll
        for (int kk = 0; kk < LBK; kk += 8) {
            wmma::fragment<wmma::matrix_a, 16, 16, 8, wmma::precision::tf32, wmma::row_major> a[2];
            wmma::fragment<wmma::matrix_b, 16, 16, 8, wmma::precision::tf32, wmma::row_major> bfrag[4];
            #pragma unroll
            for (int i = 0; i < 2; i++)
                wmma::load_matrix_sync(a[i], &as[(wr*32 + i*16)*LLDA + kk], LLDA);
            #pragma unroll
            for (int j = 0; j < 4; j++)
                wmma::load_matrix_sync(bfrag[j], &bs[kk*LLDB + wc*64 + j*16], LLDB);
            #pragma unroll
            for (int i = 0; i < 2; i++)
                #pragma unroll
                for (int j = 0; j < 4; j++)
                    wmma::mma_sync(c[i][j], a[i], bfrag[j], c[i][j]);
        }
        __syncthreads();
    }

    #pragma unroll
    for (int i = 0; i < 2; i++)
        #pragma unroll
        for (int j = 0; j < 4; j++)
            wmma::store_matrix_sync(&Cs[(wr*32 + i*16)*LLDC + wc*64 + j*16],
                                    c[i][j], LLDC, wmma::mem_row_major);
    __syncthreads();

    float4 bv0 = *(const float4*)&bias[lane*8];
    float4 bv1 = *(const float4*)&bias[lane*8 + 4];
    float4 gv0 = *(const float4*)&gam[lane*8];
    float4 gv1 = *(const float4*)&gam[lane*8 + 4];
    float4 tv0 = *(const float4*)&bet[lane*8];
    float4 tv1 = *(const float4*)&bet[lane*8 + 4];

    #pragma unroll
    for (int i = 0; i < 8; i++) {
        int r = wid*8 + i;
        int m = m0 + r;
        float4 c0 = *(float4*)&Cs[r*LLDC + lane*8];
        float4 c1 = *(float4*)&Cs[r*LLDC + lane*8 + 4];
        float4 q0 = *(const float4*)&resid[(size_t)m*CDIM + lane*8];
        float4 q1 = *(const float4*)&resid[(size_t)m*CDIM + lane*8 + 4];
        float x0 = q0.x + c0.x + bv0.x, x1 = q0.y + c0.y + bv0.y;
        float x2 = q0.z + c0.z + bv0.z, x3 = q0.w + c0.w + bv0.w;
        float x4 = q1.x + c1.x + bv1.x, x5 = q1.y + c1.y + bv1.y;
        float x6 = q1.z + c1.z + bv1.z, x7 = q1.w + c1.w + bv1.w;
        float s = x0+x1+x2+x3+x4+x5+x6+x7;
        #pragma unroll
        for (int o = 16; o > 0; o >>= 1) s += __shfl_xor_sync(0xffffffffu, s, o);
        float mean = s * (1.f/CDIM);
        float d0 = x0-mean, d1 = x1-mean, d2 = x2-mean, d3 = x3-mean;
        float d4 = x4-mean, d5 = x5-mean, d6 = x6-mean, d7 = x7-mean;
        float sq = d0*d0+d1*d1+d2*d2+d3*d3+d4*d4+d5*d5+d6*d6+d7*d7;
        #pragma unroll
        for (int o = 16; o > 0; o >>= 1) sq += __shfl_xor_sync(0xffffffffu, sq, o);
        float rstd = rsqrtf(sq * (1.f/CDIM) + 1e-5f);
        float o0 = d0*rstd*gv0.x + tv0.x, o1 = d1*rstd*gv0.y + tv0.y;
        float o2 = d2*rstd*gv0.z + tv0.z, o3 = d3*rstd*gv0.w + tv0.w;
        float o4 = d4*rstd*gv1.x + tv1.x, o5 = d5*rstd*gv1.y + tv1.y;
        float o6 = d6*rstd*gv1.z + tv1.z, o7 = d7*rstd*gv1.w + tv1.w;
        *(float4*)&outp[(size_t)m*CDIM + lane*8]     = make_float4(o0, o1, o2, o3);
        *(float4*)&outp[(size_t)m*CDIM + lane*8 + 4] = make_float4(o4, o5, o6, o7);
        *(float4*)&ornd[(size_t)m*CDIM + lane*8]     = make_float4(tf32r(o0), tf32r(o1), tf32r(o2), tf32r(o3));
        *(float4*)&ornd[(size_t)m*CDIM + lane*8 + 4] = make_float4(tf32r(o4), tf32r(o5), tf32r(o6), tf32r(o7));
    }
}

// ---------------- geometry / prep ------------------------------------------------
__global__ void k_invert(const float* __restrict__ extr) {
    int c = threadIdx.x;
    if (c >= NCAM) return;
    float a[4][8];
    for (int i = 0; i < 4; i++)
        for (int j = 0; j < 4; j++) {
            a[i][j] = extr[c*16 + i*4 + j];
            a[i][j+4] = (i == j) ? 1.f : 0.f;
        }
    for (int col = 0; col < 4; col++) {
        int piv = col;
        for (int r = col+1; r < 4; r++)
            if (fabsf(a[r][col]) > fabsf(a[piv][col])) piv = r;
        if (piv != col)
            for (int j = 0; j < 8; j++) { float t = a[col][j]; a[col][j] = a[piv][j]; a[piv][j] = t; }
        float d = 1.f / a[col][col];
        for (int j = 0; j < 8; j++) a[col][j] *= d;
        for (int r = 0; r < 4; r++) {
            if (r == col) continue;
            float f = a[r][col];
            for (int j = 0; j < 8; j++) a[r][j] -= f * a[col][j];
        }
    }
    for (int i = 0; i < 4; i++)
        for (int j = 0; j < 4; j++)
            g_inv[c*16 + i*4 + j] = a[i][j+4];
}

__global__ void k_geom(const float* __restrict__ intr) {
    int idx = blockIdx.x * blockDim.x + threadIdx.x;
    if (idx >= NCAM*NQ*NPTS) return;
    int p = idx % NPTS;
    int n = (idx / NPTS) % NQ;
    int c = idx / (NPTS * NQ);
    float gx = ((n & 127) + 0.5f) / 128.f;
    float gy = ((n >> 7)  + 0.5f) / 128.f;
    float xm = -51.2f + gx * 102.4f;
    float ym = -51.2f + gy * 102.4f;
    float zm = -5.0f + (p + 0.5f) * 2.0f;
    const float* Mi = &g_inv[c*16];
    float px = Mi[0]*xm + Mi[1]*ym + Mi[2]*zm  + Mi[3];
    float py = Mi[4]*xm + Mi[5]*ym + Mi[6]*zm  + Mi[7];
    float pz = Mi[8]*xm + Mi[9]*ym + Mi[10]*zm + Mi[11];
    const float* I = &intr[c*9];
    float ix = I[0]*px + I[1]*py + I[2]*pz;
    float iy = I[3]*px + I[4]*py + I[5]*pz;
    float iz = I[6]*px + I[7]*py + I[8]*pz;
    float zc = fmaxf(iz, 1e-5f);
    float un = ix / (zc * WF);
    float vn = iy / (zc * HF);
    float val = (iz > 1e-5f && un >= 0.f && un <= 1.f && vn >= 0.f && vn <= 1.f) ? 1.f : 0.f;
    g_refcam[idx*2+0] = un;
    g_refcam[idx*2+1] = vn;
    g_valid[idx] = val;
}

__global__ void k_cnt() {
    int n = blockIdx.x * blockDim.x + threadIdx.x;
    if (n >= NQ) return;
    float s = 0.f;
    for (int c = 0; c < NCAM; c++)
        for (int p = 0; p < NPTS; p++)
            s += g_valid[(c*NQ + n)*NPTS + p];
    g_cnt[n] = fmaxf(s, 1.f);
}

__global__ void k_feats_t(const float* __restrict__ in) {
    __shared__ float tile[32][33];
    int pix0 = blockIdx.x * 32, ch0 = blockIdx.y * 32, c = blockIdx.z;
    int tx = threadIdx.x, ty = threadIdx.y;
    for (int i = ty; i < 32; i += 8) {
        int pix = pix0 + tx;
        tile[i][tx] = (pix < NPIX) ? in[((size_t)c*CDIM + ch0 + i)*NPIX + pix] : 0.f;
    }
    __syncthreads();
    for (int i = ty; i < 32; i += 8) {
        int pix = pix0 + i;
        if (pix < NPIX)
            g_feats[((size_t)c*NPIX + pix)*CDIM + ch0 + tx] = tf32r(tile[tx][i]);
    }
}

__global__ void k_round(const float* __restrict__ W, float* __restrict__ out, int n) {
    int i = blockIdx.x * blockDim.x + threadIdx.x;
    if (i < n) out[i] = tf32r(W[i]);
}

__global__ void k_prep_oa(const float* __restrict__ tow, const float* __restrict__ taw,
                          const float* __restrict__ sow, const float* __restrict__ saw,
                          const float* __restrict__ tob, const float* __restrict__ tab,
                          const float* __restrict__ sob, const float* __restrict__ sab) {
    int idx = blockIdx.x * blockDim.x + threadIdx.x;
    int total = 2*NLAYERS*CDIM*128;
    if (idx < total) {
        int n = idx % 128;
        int k = (idx / 128) % CDIM;
        int l = (idx / (128*CDIM)) % NLAYERS;
        int s = idx / (128*CDIM*NLAYERS);
        const float* ow = s ? sow : tow;
        const float* aw = s ? saw : taw;
        float w = 0.f;
        if (n < 64)      w = ow[((size_t)l*CDIM + k)*64 + n];
        else if (n < 96) w = aw[((size_t)l*CDIM + k)*32 + (n - 64)];
        g_oaw[idx] = tf32r(w);
    }
    if (idx < 2*NLAYERS*128) {
        int j = idx % 128;
        int l = (idx / 128) % NLAYERS;
        int s = idx / (128*NLAYERS);
        const float* ob = s ? sob : tob;
        const float* ab = s ? sab : tab;
        float b = 0.f;
        if (j < 64)      b = ob[l*64 + j];
        else if (j < 96) b = ab[l*32 + (j - 64)];
        g_oab[idx] = b;
    }
}

__global__ void k_init_q(const float* __restrict__ src) {
    int i = blockIdx.x * blockDim.x + threadIdx.x;
    if (i >= NQ*CDIM) return;
    float v = src[i];
    g_q[i] = v;
    g_q_rnd[i] = tf32r(v);
}

// ---------------- samplers --------------------------------------------------------
__device__ __forceinline__ float bilin(const float* __restrict__ base, int H, int W,
                                       int stride, float ix, float iy) {
    float x0f = floorf(ix), y0f = floorf(iy);
    int x0 = (int)x0f, y0 = (int)y0f;
    float fx = ix - x0f, fy = iy - y0f;
    float out = 0.f;
    #pragma unroll
    for (int dy = 0; dy < 2; dy++) {
        int yi = y0 + dy;
        if (yi < 0 || yi >= H) continue;
        float wy = dy ? fy : 1.f - fy;
        #pragma unroll
        for (int dx = 0; dx < 2; dx++) {
            int xi = x0 + dx;
            if (xi < 0 || xi >= W) continue;
            float wx = dx ? fx : 1.f - fx;
            out += wy * wx * base[((size_t)yi*W + xi) * stride];
        }
    }
    return out;
}

__global__ void k_tsa_sample() {
    int n = blockIdx.x;
    int h = threadIdx.x >> 5;
    int lane = threadIdx.x & 31;
    const float* oa = &g_offattn[n*96];
    float lg0 = oa[64 + h*4 + 0], lg1 = oa[64 + h*4 + 1];
    float lg2 = oa[64 + h*4 + 2], lg3 = oa[64 + h*4 + 3];
    float mx = fmaxf(fmaxf(lg0, lg1), fmaxf(lg2, lg3));
    float e0 = expf(lg0-mx), e1 = expf(lg1-mx), e2 = expf(lg2-mx), e3 = expf(lg3-mx);
    float rse = 1.f / (e0+e1+e2+e3);
    float w[4] = {e0*rse, e1*rse, e2*rse, e3*rse};
    float refx = ((n & 127) + 0.5f);
    float refy = ((n >> 7)  + 0.5f);
    const float* base = g_v + h*HD + lane;
    float acc = 0.f;
    #pragma unroll
    for (int p = 0; p < 4; p++) {
        float ox = oa[(h*4 + p)*2 + 0];
        float oy = oa[(h*4 + p)*2 + 1];
        acc += w[p] * bilin(base, 128, 128, CDIM, refx + ox - 0.5f, refy + oy - 0.5f);
    }
    g_a[(size_t)n*CDIM + h*HD + lane] = tf32r(acc);
}

__global__ void k_sca_sample() {
    int n = blockIdx.x;
    int h = threadIdx.x >> 5;
    int lane = threadIdx.x & 31;
    const float* oa = &g_offattn[n*96];
    float lg0 = oa[64 + h*4 + 0], lg1 = oa[64 + h*4 + 1];
    float lg2 = oa[64 + h*4 + 2], lg3 = oa[64 + h*4 + 3];
    float mx = fmaxf(fmaxf(lg0, lg1), fmaxf(lg2, lg3));
    float e0 = expf(lg0-mx), e1 = expf(lg1-mx), e2 = expf(lg2-mx), e3 = expf(lg3-mx);
    float rse = 1.f / (e0+e1+e2+e3);
    float w[4], ox[4], oy[4];
    w[0] = e0*rse; w[1] = e1*rse; w[2] = e2*rse; w[3] = e3*rse;
    #pragma unroll
    for (int p = 0; p < 4; p++) {
        ox[p] = oa[(h*4 + p)*2 + 0];
        oy[p] = oa[(h*4 + p)*2 + 1];
    }
    float acc = 0.f;
    for (int c = 0; c < NCAM; c++) {
        const float* rc = &g_refcam[((size_t)(c*NQ + n))*NPTS*2];
        const float* vv = &g_valid[((size_t)(c*NQ + n))*NPTS];
        const float* base = g_vimg + (size_t)c*NPIX*CDIM + h*HD + lane;
        #pragma unroll
        for (int p = 0; p < 4; p++) {
            if (vv[p] == 0.f) continue;
            float ix = rc[p*2+0]*WF + ox[p] - 0.5f;
            float iy = rc[p*2+1]*HF + oy[p] - 0.5f;
            acc += w[p] * bilin(base, HF, WF, CDIM, ix, iy);
        }
    }
    g_a[(size_t)n*CDIM + h*HD + lane] = tf32r(acc / g_cnt[n]);
}

__global__ void k_out_t(float* __restrict__ out) {
    __shared__ float tile[32][33];
    int n0 = blockIdx.x * 32, c0 = blockIdx.y * 32;
    int tx = threadIdx.x, ty = threadIdx.y;
    for (int i = ty; i < 32; i += 8)
        tile[i][tx] = g_q[(size_t)(n0 + i)*CDIM + c0 + tx];
    __syncthreads();
    for (int i = ty; i < 32; i += 8)
        out[(size_t)(c0 + i)*NQ + n0 + tx] = tile[tx][i];
}

// ---------------- host --------------------------------------------------------
static void gemm128(const float* A, const float* B, const float* bias, float* out,
                    int M, int N, int K, int ldb, bool relu) {
    dim3 g((M + TBM - 1) / TBM, (ldb + TBN - 1) / TBN);
    if (relu) k_gemm128<1, false><<<g, 256, T_SMEM>>>(A, A, B, bias, out, M, N, K, ldb);
    else      k_gemm128<0, false><<<g, 256, T_SMEM>>>(A, A, B, bias, out, M, N, K, ldb);
}
static void gemm128_avg(const float* A, const float* A2, const float* B,
                        const float* bias, float* out, int M, int N, int K, int ldb) {
    dim3 g((M + TBM - 1) / TBM, (ldb + TBN - 1) / TBN);
    k_gemm128<0, true><<<g, 256, T_SMEM>>>(A, A2, B, bias, out, M, N, K, ldb);
}
static void gemm_ln(const float* A, const float* W, const float* bias,
                    const float* resid, const float* gam, const float* bet,
                    float* outp, float* ornd, int M, int K) {
    k_gemm_ln<<<M / LM, 256, L_SMEM>>>(A, W, bias, resid, gam, bet, outp, ornd, M, K);
}

extern "C" void kernel_launch(void* const* d_in, const int* in_sizes, int n_in,
                              void* d_out, int out_size) {
    static bool attr_set = false;
    if (!attr_set) {
        cudaFuncSetAttribute((const void*)k_gemm128<0, false>, cudaFuncAttributeMaxDynamicSharedMemorySize, T_SMEM);
        cudaFuncSetAttribute((const void*)k_gemm128<1, false>, cudaFuncAttributeMaxDynamicSharedMemorySize, T_SMEM);
        cudaFuncSetAttribute((const void*)k_gemm128<0, true>,  cudaFuncAttributeMaxDynamicSharedMemorySize, T_SMEM);
        cudaFuncSetAttribute((const void*)k_gemm_ln,           cudaFuncAttributeMaxDynamicSharedMemorySize, L_SMEM);
        attr_set = true;
    }

    const float* image_feats = (const float*)d_in[0];
    const float* intr        = (const float*)d_in[1];
    const float* extr        = (const float*)d_in[2];
    const float* prev        = (const float*)d_in[3];
    const float* bev         = (const float*)d_in[4];
    const float* tsa_vw = (const float*)d_in[5];
    const float* tsa_vb = (const float*)d_in[6];
    const float* tsa_pw = (const float*)d_in[11];
    const float* tsa_pb = (const float*)d_in[12];
    const float* sca_vw = (const float*)d_in[13];
    const float* sca_vb = (const float*)d_in[14];
    const float* sca_pw = (const float*)d_in[19];
    const float* sca_pb = (const float*)d_in[20];
    const float* ffn_w1 = (const float*)d_in[21];
    const float* ffn_b1 = (const float*)d_in[22];
    const float* ffn_w2 = (const float*)d_in[23];
    const float* ffn_b2 = (const float*)d_in[24];
    const float* ln1_g  = (const float*)d_in[25];
    const float* ln1_b  = (const float*)d_in[26];
    const float* ln2_g  = (const float*)d_in[27];
    const float* ln2_b  = (const float*)d_in[28];
    const float* ln3_g  = (const float*)d_in[29];
    const float* ln3_b  = (const float*)d_in[30];

    float *q_, *qr_, *a_, *hid_, *v_, *vimg_, *oa_, *feats_;
    float *tvw_, *tpw_, *svw_, *spw_, *f1w_, *f2w_, *oaw_, *oab_;
    cudaGetSymbolAddress((void**)&q_,    g_q);
    cudaGetSymbolAddress((void**)&qr_,   g_q_rnd);
    cudaGetSymbolAddress((void**)&a_,    g_a);
    cudaGetSymbolAddress((void**)&hid_,  g_hid);
    cudaGetSymbolAddress((void**)&v_,    g_v);
    cudaGetSymbolAddress((void**)&vimg_, g_vimg);
    cudaGetSymbolAddress((void**)&oa_,   g_offattn);
    cudaGetSymbolAddress((void**)&feats_, g_feats);
    cudaGetSymbolAddress((void**)&tvw_,  g_tvw);
    cudaGetSymbolAddress((void**)&tpw_,  g_tpw);
    cudaGetSymbolAddress((void**)&svw_,  g_svw);
    cudaGetSymbolAddress((void**)&spw_,  g_spw);
    cudaGetSymbolAddress((void**)&f1w_,  g_f1w);
    cudaGetSymbolAddress((void**)&f2w_,  g_f2w);
    cudaGetSymbolAddress((void**)&oaw_,  g_oaw);
    cudaGetSymbolAddress((void**)&oab_,  g_oab);

    const int WB = 256;
    {
        dim3 gt((NPIX + 31)/32, CDIM/32, NCAM);
        k_feats_t<<<gt, dim3(32, 8)>>>(image_feats);                      // 1
    }
    k_round<<<(NLAYERS*CDIM*CDIM + WB-1)/WB, WB>>>(sca_vw, svw_, NLAYERS*CDIM*CDIM);  // 2
    k_invert<<<1, NCAM>>>(extr);                                          // 3
    gemm128(feats_, svw_, sca_vb, vimg_, NFEAT, CDIM, CDIM, CDIM, false); // 4 (profile slot)
    k_geom<<<(NCAM*NQ*NPTS + 255)/256, 256>>>(intr);
    k_cnt<<<(NQ + 255)/256, 256>>>();
    k_round<<<(NLAYERS*CDIM*CDIM + WB-1)/WB, WB>>>(tsa_vw, tvw_, NLAYERS*CDIM*CDIM);
    k_round<<<(NLAYERS*CDIM*CDIM + WB-1)/WB, WB>>>(tsa_pw, tpw_, NLAYERS*CDIM*CDIM);
    k_round<<<(NLAYERS*CDIM*CDIM + WB-1)/WB, WB>>>(sca_pw, spw_, NLAYERS*CDIM*CDIM);
    k_round<<<(NLAYERS*CDIM*FFN + WB-1)/WB, WB>>>(ffn_w1, f1w_, NLAYERS*CDIM*FFN);
    k_round<<<(NLAYERS*FFN*CDIM + WB-1)/WB, WB>>>(ffn_w2, f2w_, NLAYERS*FFN*CDIM);
    k_prep_oa<<<(2*NLAYERS*CDIM*128 + WB-1)/WB, WB>>>(
        (const float*)d_in[7], (const float*)d_in[9],
        (const float*)d_in[15], (const float*)d_in[17],
        (const float*)d_in[8], (const float*)d_in[10],
        (const float*)d_in[16], (const float*)d_in[18]);
    k_init_q<<<(NQ*CDIM + 255)/256, 256>>>(bev);

    for (int l = 0; l < NLAYERS; l++) {
        size_t wo = (size_t)l*CDIM*CDIM;
        // ---- TSA ----
        gemm128_avg(q_, prev, tvw_ + wo, tsa_vb + l*CDIM, v_, NQ, CDIM, CDIM, CDIM);
        gemm128(qr_, oaw_ + (size_t)l*CDIM*128, oab_ + l*128, oa_, NQ, 96, CDIM, 128, false);
        k_tsa_sample<<<NQ, 256>>>();
        gemm_ln(a_, tpw_ + wo, tsa_pb + l*CDIM, q_, ln1_g + l*CDIM, ln1_b + l*CDIM,
                q_, qr_, NQ, CDIM);

        // ---- SCA ----
        if (l > 0)
            gemm128(feats_, svw_ + wo, sca_vb + l*CDIM, vimg_, NFEAT, CDIM, CDIM, CDIM, false);
        gemm128(qr_, oaw_ + (size_t)(NLAYERS + l)*CDIM*128, oab_ + (NLAYERS + l)*128,
                oa_, NQ, 96, CDIM, 128, false);
        k_sca_sample<<<NQ, 256>>>();
        gemm_ln(a_, spw_ + wo, sca_pb + l*CDIM, q_, ln2_g + l*CDIM, ln2_b + l*CDIM,
                q_, qr_, NQ, CDIM);

        // ---- FFN ----
        gemm128(qr_, f1w_ + (size_t)l*CDIM*FFN, ffn_b1 + l*FFN, hid_, NQ, FFN, CDIM, FFN, true);
        gemm_ln(hid_, f2w_ + (size_t)l*FFN*CDIM, ffn_b2 + l*CDIM, q_,
                ln3_g + l*CDIM, ln3_b + l*CDIM, q_, qr_, NQ, FFN);
    }

    k_out_t<<<dim3(NQ/32, CDIM/32), dim3(32, 8)>>>((float*)d_out);
}